// round 1
// baseline (speedup 1.0000x reference)
#include <cuda_runtime.h>
#include <math.h>

#define D_MODEL 1024
#define N_HEADS 16
#define D_FF    4096
#define BB      2
#define SS      2048
#define DK      64
#define ROWS    (BB*SS)          /* 4096 */
#define LN_EPS  1e-6f

/* ---------------- scratch (no allocations allowed) ---------------- */
__device__ float g_Q  [ROWS*D_MODEL];
__device__ float g_K  [ROWS*D_MODEL];
__device__ float g_V  [ROWS*D_MODEL];
__device__ float g_ctx[ROWS*D_MODEL];
__device__ float g_tmp[ROWS*D_MODEL];
__device__ float g_ao [ROWS*D_MODEL];
__device__ float g_f1 [ROWS*D_FF];
__device__ float g_f2 [ROWS*D_MODEL];

/* ---------------- generic batched SGEMM ----------------
 * C = relu? max(0, scale*A*B + bias) : scale*A*B + bias
 * A: [M,K] row-major (lda). B: TRANS_B ? [N,K] (ldb) : [K,N] (ldb).
 * batch offset for matrix X: (z/HB)*sX0 + (z%HB)*sX1
 * Tiles: 128x128x8, 256 threads, 8x8 per thread (4-split for
 * conflict-free float4 smem reads).
 */
#define BM 128
#define BN 128
#define BK 8

template<bool TRANS_B>
__global__ void __launch_bounds__(256, 2)
sgemm_kernel(const float* __restrict__ A, const float* __restrict__ B,
             const float* __restrict__ bias, float* __restrict__ C,
             int M, int N, int K, int lda, int ldb, int ldc,
             int HB,
             long long sA0, long long sA1,
             long long sB0, long long sB1,
             long long sC0, long long sC1,
             float scale, int relu)
{
    const int z = blockIdx.z;
    A += (long long)(z / HB) * sA0 + (long long)(z % HB) * sA1;
    B += (long long)(z / HB) * sB0 + (long long)(z % HB) * sB1;
    C += (long long)(z / HB) * sC0 + (long long)(z % HB) * sC1;

    __shared__ float As[BK][BM];
    __shared__ float Bs[BK][BN];

    const int tid = threadIdx.x;
    const int tr  = tid >> 4;      /* 0..15 */
    const int tc  = tid & 15;      /* 0..15 */
    const int row0 = blockIdx.y * BM;
    const int col0 = blockIdx.x * BN;

    float acc[8][8];
#pragma unroll
    for (int i = 0; i < 8; i++)
#pragma unroll
        for (int j = 0; j < 8; j++) acc[i][j] = 0.f;

    for (int k0 = 0; k0 < K; k0 += BK) {
        /* A tile: BM*BK = 1024 floats, one float4 per thread */
        {
            const int e  = tid * 4;
            const int m  = e >> 3;
            const int kk = e & 7;
            const int gm = row0 + m;
            float4 v = make_float4(0.f, 0.f, 0.f, 0.f);
            if (gm < M)
                v = *reinterpret_cast<const float4*>(&A[(long long)gm * lda + k0 + kk]);
            As[kk + 0][m] = v.x; As[kk + 1][m] = v.y;
            As[kk + 2][m] = v.z; As[kk + 3][m] = v.w;
        }
        /* B tile */
        if (!TRANS_B) {
            const int e  = tid * 4;
            const int kk = e >> 7;
            const int n  = e & 127;
            const int gn = col0 + n;
            float4 v = make_float4(0.f, 0.f, 0.f, 0.f);
            if (gn < N)  /* N % 4 == 0 in this problem */
                v = *reinterpret_cast<const float4*>(&B[(long long)(k0 + kk) * ldb + gn]);
            *reinterpret_cast<float4*>(&Bs[kk][n]) = v;
        } else {
            const int e  = tid * 4;
            const int n  = e >> 3;
            const int kk = e & 7;
            const int gn = col0 + n;
            float4 v = make_float4(0.f, 0.f, 0.f, 0.f);
            if (gn < N)
                v = *reinterpret_cast<const float4*>(&B[(long long)gn * ldb + k0 + kk]);
            Bs[kk + 0][n] = v.x; Bs[kk + 1][n] = v.y;
            Bs[kk + 2][n] = v.z; Bs[kk + 3][n] = v.w;
        }
        __syncthreads();

#pragma unroll
        for (int kk = 0; kk < BK; kk++) {
            float4 a0 = *reinterpret_cast<const float4*>(&As[kk][tr * 4]);
            float4 a1 = *reinterpret_cast<const float4*>(&As[kk][64 + tr * 4]);
            float4 b0 = *reinterpret_cast<const float4*>(&Bs[kk][tc * 4]);
            float4 b1 = *reinterpret_cast<const float4*>(&Bs[kk][64 + tc * 4]);
            float a[8] = {a0.x, a0.y, a0.z, a0.w, a1.x, a1.y, a1.z, a1.w};
            float b[8] = {b0.x, b0.y, b0.z, b0.w, b1.x, b1.y, b1.z, b1.w};
#pragma unroll
            for (int i = 0; i < 8; i++)
#pragma unroll
                for (int j = 0; j < 8; j++) acc[i][j] += a[i] * b[j];
        }
        __syncthreads();
    }

    /* epilogue: rows {tr*4+i, 64+tr*4+i}, cols {tc*4+j, 64+tc*4+j} */
#pragma unroll
    for (int i = 0; i < 8; i++) {
        const int gm = row0 + ((i < 4) ? (tr * 4 + i) : (64 + tr * 4 + i - 4));
        if (gm >= M) continue;
#pragma unroll
        for (int jc = 0; jc < 2; jc++) {
            const int gn = col0 + (jc ? (64 + tc * 4) : (tc * 4));
            if (gn >= N) continue;
            float4 v;
            v.x = acc[i][jc * 4 + 0] * scale;
            v.y = acc[i][jc * 4 + 1] * scale;
            v.z = acc[i][jc * 4 + 2] * scale;
            v.w = acc[i][jc * 4 + 3] * scale;
            if (bias) {
                float4 bb = *reinterpret_cast<const float4*>(&bias[gn]);
                v.x += bb.x; v.y += bb.y; v.z += bb.z; v.w += bb.w;
            }
            if (relu) {
                v.x = fmaxf(v.x, 0.f); v.y = fmaxf(v.y, 0.f);
                v.z = fmaxf(v.z, 0.f); v.w = fmaxf(v.w, 0.f);
            }
            *reinterpret_cast<float4*>(&C[(long long)gm * ldc + gn]) = v;
        }
    }
}

/* ---------------- softmax over rows of length SS, in place ---------------- */
__global__ void softmax_kernel(float* __restrict__ attn)
{
    __shared__ float srow[SS];
    __shared__ float red[256];
    const int tid = threadIdx.x;
    float* row = attn + (long long)blockIdx.x * SS;

    float mx = -1e30f;
    for (int j = tid; j < SS; j += 256) {
        float t = row[j];
        srow[j] = t;
        mx = fmaxf(mx, t);
    }
    red[tid] = mx; __syncthreads();
    for (int s = 128; s > 0; s >>= 1) {
        if (tid < s) red[tid] = fmaxf(red[tid], red[tid + s]);
        __syncthreads();
    }
    mx = red[0];
    __syncthreads();

    float sum = 0.f;
    for (int j = tid; j < SS; j += 256) {
        float e = __expf(srow[j] - mx);
        srow[j] = e;
        sum += e;
    }
    red[tid] = sum; __syncthreads();
    for (int s = 128; s > 0; s >>= 1) {
        if (tid < s) red[tid] += red[tid + s];
        __syncthreads();
    }
    const float inv = 1.f / red[0];
    __syncthreads();
    for (int j = tid; j < SS; j += 256) row[j] = srow[j] * inv;
}

/* ------------- out = alpha*(v-mean)/(std+eps)+beta, v = x+y -------------
 * std is Bessel-corrected: sqrt(sum(c^2)/(D-1)), divisor is (std + eps). */
__global__ void add_ln_kernel(const float* __restrict__ x, const float* __restrict__ y,
                              const float* __restrict__ alpha, const float* __restrict__ beta,
                              float* __restrict__ out)
{
    __shared__ float v[D_MODEL];
    __shared__ float red[256];
    const int tid = threadIdx.x;
    const long long base = (long long)blockIdx.x * D_MODEL;

    float s = 0.f;
    for (int j = tid; j < D_MODEL; j += 256) {
        float t = x[base + j] + y[base + j];
        v[j] = t;
        s += t;
    }
    red[tid] = s; __syncthreads();
    for (int st = 128; st > 0; st >>= 1) {
        if (tid < st) red[tid] += red[tid + st];
        __syncthreads();
    }
    const float m = red[0] * (1.f / D_MODEL);
    __syncthreads();

    float c2 = 0.f;
    for (int j = tid; j < D_MODEL; j += 256) {
        float c = v[j] - m;
        c2 += c * c;
    }
    red[tid] = c2; __syncthreads();
    for (int st = 128; st > 0; st >>= 1) {
        if (tid < st) red[tid] += red[tid + st];
        __syncthreads();
    }
    const float stdv = sqrtf(red[0] / (float)(D_MODEL - 1));
    const float inv  = 1.f / (stdv + LN_EPS);
    for (int j = tid; j < D_MODEL; j += 256)
        out[base + j] = alpha[j] * (v[j] - m) * inv + beta[j];
}

/* ---------------- host dispatch ---------------- */
static void run_gemm(bool transB, const float* A, const float* B, const float* bias,
                     float* C, int M, int N, int K, int lda, int ldb, int ldc,
                     int batch, int HB,
                     long long sA0, long long sA1,
                     long long sB0, long long sB1,
                     long long sC0, long long sC1,
                     float scale, int relu)
{
    dim3 grid((N + BN - 1) / BN, (M + BM - 1) / BM, batch);
    dim3 block(256);
    if (transB)
        sgemm_kernel<true><<<grid, block>>>(A, B, bias, C, M, N, K, lda, ldb, ldc,
                                            HB, sA0, sA1, sB0, sB1, sC0, sC1, scale, relu);
    else
        sgemm_kernel<false><<<grid, block>>>(A, B, bias, C, M, N, K, lda, ldb, ldc,
                                             HB, sA0, sA1, sB0, sB1, sC0, sC1, scale, relu);
}

extern "C" void kernel_launch(void* const* d_in, const int* in_sizes, int n_in,
                              void* d_out, int out_size)
{
    const float* x   = (const float*)d_in[0];
    const float* Wq  = (const float*)d_in[1];
    const float* bq  = (const float*)d_in[2];
    const float* Wk  = (const float*)d_in[3];
    const float* bk  = (const float*)d_in[4];
    const float* Wv  = (const float*)d_in[5];
    const float* bv  = (const float*)d_in[6];
    const float* Wo  = (const float*)d_in[7];
    const float* bo  = (const float*)d_in[8];
    const float* W1  = (const float*)d_in[9];
    const float* b1  = (const float*)d_in[10];
    const float* W2  = (const float*)d_in[11];
    const float* b2  = (const float*)d_in[12];
    const float* a1  = (const float*)d_in[13];
    const float* be1 = (const float*)d_in[14];
    const float* a2  = (const float*)d_in[15];
    const float* be2 = (const float*)d_in[16];

    float* out  = (float*)d_out;
    float* enc  = out;                                  /* [B,S,D]      */
    float* attn = out + (size_t)ROWS * D_MODEL;          /* [B,H,S,S]    */

    float *Q, *Km, *V, *CTX, *TMP, *AO, *F1, *F2;
    cudaGetSymbolAddress((void**)&Q,   g_Q);
    cudaGetSymbolAddress((void**)&Km,  g_K);
    cudaGetSymbolAddress((void**)&V,   g_V);
    cudaGetSymbolAddress((void**)&CTX, g_ctx);
    cudaGetSymbolAddress((void**)&TMP, g_tmp);
    cudaGetSymbolAddress((void**)&AO,  g_ao);
    cudaGetSymbolAddress((void**)&F1,  g_f1);
    cudaGetSymbolAddress((void**)&F2,  g_f2);

    const long long sBD  = (long long)SS * D_MODEL;   /* per-b stride in Q/K/V/ctx */
    const long long sSS  = (long long)SS * SS;        /* per-head stride in attn   */

    /* 1) Q/K/V projections: [4096,1024] = x @ W + b */
    run_gemm(false, x, Wq, bq, Q,  ROWS, D_MODEL, D_MODEL, D_MODEL, D_MODEL, D_MODEL,
             1, 1, 0, 0, 0, 0, 0, 0, 1.f, 0);
    run_gemm(false, x, Wk, bk, Km, ROWS, D_MODEL, D_MODEL, D_MODEL, D_MODEL, D_MODEL,
             1, 1, 0, 0, 0, 0, 0, 0, 1.f, 0);
    run_gemm(false, x, Wv, bv, V,  ROWS, D_MODEL, D_MODEL, D_MODEL, D_MODEL, D_MODEL,
             1, 1, 0, 0, 0, 0, 0, 0, 1.f, 0);

    /* 2) scores = Q K^T / 8  -> attn region of d_out (batched over b*h) */
    run_gemm(true, Q, Km, nullptr, attn, SS, SS, DK, D_MODEL, D_MODEL, SS,
             BB * N_HEADS, N_HEADS,
             sBD, DK,            /* A offsets: b*S*D + h*64 */
             sBD, DK,            /* B offsets: same         */
             (long long)N_HEADS * sSS, sSS,
             0.125f, 0);

    /* 3) softmax in place over last dim */
    softmax_kernel<<<BB * N_HEADS * SS, 256>>>(attn);

    /* 4) ctx = attn @ V  -> [B*S, D] layout (batched) */
    run_gemm(false, attn, V, nullptr, CTX, SS, DK, SS, SS, D_MODEL, D_MODEL,
             BB * N_HEADS, N_HEADS,
             (long long)N_HEADS * sSS, sSS,
             sBD, DK,
             sBD, DK,
             1.f, 0);

    /* 5) proj = ctx @ Wo + bo */
    run_gemm(false, CTX, Wo, bo, TMP, ROWS, D_MODEL, D_MODEL, D_MODEL, D_MODEL, D_MODEL,
             1, 1, 0, 0, 0, 0, 0, 0, 1.f, 0);

    /* 6) attn_out = LN(x + proj) */
    add_ln_kernel<<<ROWS, 256>>>(x, TMP, a1, be1, AO);

    /* 7) ff1 = relu(attn_out @ W1 + b1) */
    run_gemm(false, AO, W1, b1, F1, ROWS, D_FF, D_MODEL, D_MODEL, D_FF, D_FF,
             1, 1, 0, 0, 0, 0, 0, 0, 1.f, 1);

    /* 8) ff2 = ff1 @ W2 + b2 */
    run_gemm(false, F1, W2, b2, F2, ROWS, D_MODEL, D_FF, D_FF, D_MODEL, D_MODEL,
             1, 1, 0, 0, 0, 0, 0, 0, 1.f, 0);

    /* 9) enc_out = LN(attn_out + ff2) */
    add_ln_kernel<<<ROWS, 256>>>(AO, F2, a2, be2, enc);

    (void)in_sizes; (void)n_in; (void)out_size;
}

// round 3
// speedup vs baseline: 1.2541x; 1.2541x over previous
#include <cuda_runtime.h>
#include <cuda_bf16.h>
#include <math.h>
#include <stdint.h>

#define D_MODEL 1024
#define N_HEADS 16
#define D_FF    4096
#define BB      2
#define SS      2048
#define DK      64
#define ROWS    (BB*SS)          /* 4096 */
#define LN_EPS  1e-6f

/* ---------------- scratch (no allocations allowed) ---------------- */
__device__ float g_Q  [ROWS*D_MODEL];
__device__ float g_K  [ROWS*D_MODEL];
__device__ float g_V  [ROWS*D_MODEL];
__device__ float g_ctx[ROWS*D_MODEL];
__device__ float g_tmp[ROWS*D_MODEL];
__device__ float g_ao [ROWS*D_MODEL];
__device__ float g_f1 [ROWS*D_FF];
__device__ float g_f2 [ROWS*D_MODEL];

/* ---------------- helpers ---------------- */
__device__ __forceinline__ uint32_t smem_u32(const void* p) {
    uint32_t a;
    asm("{ .reg .u64 t; cvta.to.shared.u64 t, %1; cvt.u32.u64 %0, t; }" : "=r"(a) : "l"(p));
    return a;
}
__device__ __forceinline__ void ldm4(uint32_t* d, uint32_t addr) {
    asm volatile("ldmatrix.sync.aligned.m8n8.x4.shared.b16 {%0,%1,%2,%3}, [%4];"
                 : "=r"(d[0]), "=r"(d[1]), "=r"(d[2]), "=r"(d[3]) : "r"(addr));
}
__device__ __forceinline__ void mma_bf16(float* c, const uint32_t* a, uint32_t b0, uint32_t b1) {
    asm volatile("mma.sync.aligned.m16n8k16.row.col.f32.bf16.bf16.f32 "
                 "{%0,%1,%2,%3}, {%4,%5,%6,%7}, {%8,%9}, {%0,%1,%2,%3};"
                 : "+f"(c[0]), "+f"(c[1]), "+f"(c[2]), "+f"(c[3])
                 : "r"(a[0]), "r"(a[1]), "r"(a[2]), "r"(a[3]), "r"(b0), "r"(b1));
}
__device__ __forceinline__ void split4(float4 v, uint2& hi, uint2& lo) {
    __nv_bfloat162 h01 = __floats2bfloat162_rn(v.x, v.y);
    __nv_bfloat162 h23 = __floats2bfloat162_rn(v.z, v.w);
    float2 f01 = __bfloat1622float2(h01);
    float2 f23 = __bfloat1622float2(h23);
    __nv_bfloat162 l01 = __floats2bfloat162_rn(v.x - f01.x, v.y - f01.y);
    __nv_bfloat162 l23 = __floats2bfloat162_rn(v.z - f23.x, v.w - f23.y);
    hi.x = *reinterpret_cast<uint32_t*>(&h01);
    hi.y = *reinterpret_cast<uint32_t*>(&h23);
    lo.x = *reinterpret_cast<uint32_t*>(&l01);
    lo.y = *reinterpret_cast<uint32_t*>(&l23);
}

/* ================= HMMA (mma.sync bf16) GEMM =================
 * C[M,N] = scale * A[M,K] @ op(B) + bias (+relu)
 * DIRECT_B: B stored [N,K] row-major -> copy K-major.
 * !DIRECT_B: B stored [K,N] row-major -> transpose while staging.
 * fp32 operands split to hi+lo bf16; acc += ah*bh + ah*bl + al*bh.
 * Tile 128 x BN_T x 32, 8 warps (4m x 2n), double-buffered smem.
 * smem row stride = 40 bf16 (80B): conflict-free ldmatrix phases.
 */
#define KSB   80                  /* bytes per smem row */
#define MATB  (128*KSB)           /* 10240 bytes per matrix half */
#define STG   (4*MATB)            /* stage stride: Ahi,Alo,Bhi,Blo */
#define SMEM_TOTAL (2*STG)        /* 81920 */

template<int BN_T, bool DIRECT_B>
__global__ void __launch_bounds__(256)
mma_gemm(const float* __restrict__ A, const float* __restrict__ B,
         const float* __restrict__ bias, float* __restrict__ C,
         int M, int N, int K, int lda, int ldb, int ldc,
         int HB,
         long long sA0, long long sA1,
         long long sB0, long long sB1,
         long long sC0, long long sC1,
         float scale, int relu)
{
    extern __shared__ char smem[];
    const int tid  = threadIdx.x;
    const int lane = tid & 31;
    const int wid  = tid >> 5;

    const int z = blockIdx.z;
    A += (long long)(z / HB) * sA0 + (long long)(z % HB) * sA1;
    B += (long long)(z / HB) * sB0 + (long long)(z % HB) * sB1;
    C += (long long)(z / HB) * sC0 + (long long)(z % HB) * sC1;

    const int row0 = blockIdx.y * 128;
    const int col0 = blockIdx.x * BN_T;

    constexpr int NFP = BN_T / 32;     /* x4 B-loads per warp per kstep */
    constexpr int BI  = BN_T / 32;     /* float4 B-prefetch per thread  */
    const int wm = wid & 3;            /* warp m index 0..3 */
    const int wn = wid >> 2;           /* warp n index 0..1 */
    const int m0 = wm * 32;
    const int n0 = wn * (BN_T / 2);

    const uint32_t sb  = smem_u32(smem);
    const int r8  = lane & 7;
    const int sel = lane >> 3;
    /* ldmatrix lane->row addresses (byte offsets within a matrix half) */
    const uint32_t aoff = (uint32_t)(m0 + (sel & 1) * 8 + r8) * KSB + (uint32_t)((sel >> 1) * 8) * 2u;
    const uint32_t boff = (uint32_t)(n0 + (sel >> 1) * 8 + r8) * KSB + (uint32_t)((sel & 1) * 8) * 2u;

    float acc[2][2 * NFP][4];
#pragma unroll
    for (int i = 0; i < 2; i++)
#pragma unroll
        for (int j = 0; j < 2 * NFP; j++)
#pragma unroll
            for (int q = 0; q < 4; q++) acc[i][j][q] = 0.f;

    float4 ar[4], br[BI];

    auto loadA = [&](int k0) {
#pragma unroll
        for (int i = 0; i < 4; i++) {
            int e = tid + i * 256;
            int rr = e >> 3, c4 = e & 7;
            ar[i] = *reinterpret_cast<const float4*>(&A[(long long)(row0 + rr) * lda + k0 + c4 * 4]);
        }
    };
    auto loadB = [&](int k0) {
        if (DIRECT_B) {
#pragma unroll
            for (int i = 0; i < BI; i++) {
                int e = tid + i * 256;
                int rr = e >> 3, c4 = e & 7;
                br[i] = *reinterpret_cast<const float4*>(&B[(long long)(col0 + rr) * ldb + k0 + c4 * 4]);
            }
        } else {
#pragma unroll
            for (int i = 0; i < BI; i++) {
                int e = tid + i * 256;
                int kk = e / (BN_T / 4), n4 = e % (BN_T / 4);
                br[i] = *reinterpret_cast<const float4*>(&B[(long long)(k0 + kk) * ldb + col0 + n4 * 4]);
            }
        }
    };
    auto storeA = [&](uint32_t stg) {
#pragma unroll
        for (int i = 0; i < 4; i++) {
            int e = tid + i * 256;
            int rr = e >> 3, c4 = e & 7;
            uint2 hi, lo;
            split4(ar[i], hi, lo);
            uint32_t off = rr * KSB + c4 * 8;
            *reinterpret_cast<uint2*>(smem + stg + off)        = hi;
            *reinterpret_cast<uint2*>(smem + stg + MATB + off) = lo;
        }
    };
    auto storeB = [&](uint32_t stg) {
        if (DIRECT_B) {
#pragma unroll
            for (int i = 0; i < BI; i++) {
                int e = tid + i * 256;
                int rr = e >> 3, c4 = e & 7;
                uint2 hi, lo;
                split4(br[i], hi, lo);
                uint32_t off = rr * KSB + c4 * 8;
                *reinterpret_cast<uint2*>(smem + stg + 2 * MATB + off) = hi;
                *reinterpret_cast<uint2*>(smem + stg + 3 * MATB + off) = lo;
            }
        } else {
#pragma unroll
            for (int i = 0; i < BI; i++) {
                int e = tid + i * 256;
                int kk = e / (BN_T / 4), n4 = e % (BN_T / 4);
                const float* f = reinterpret_cast<const float*>(&br[i]);
#pragma unroll
                for (int j = 0; j < 4; j++) {
                    int nn = n4 * 4 + j;
                    __nv_bfloat16 h = __float2bfloat16(f[j]);
                    __nv_bfloat16 l = __float2bfloat16(f[j] - __bfloat162float(h));
                    uint32_t off = nn * KSB + kk * 2;
                    *reinterpret_cast<__nv_bfloat16*>(smem + stg + 2 * MATB + off) = h;
                    *reinterpret_cast<__nv_bfloat16*>(smem + stg + 3 * MATB + off) = l;
                }
            }
        }
    };

    const int NCH = K >> 5;   /* K multiple of 32 guaranteed here */

    loadA(0); loadB(0);
    storeA(0); storeB(0);

    for (int it = 0; it < NCH; ++it) {
        __syncthreads();
        const bool more = (it + 1 < NCH);
        if (more) { loadA((it + 1) * 32); loadB((it + 1) * 32); }

        const uint32_t stg = (uint32_t)(it & 1) * STG;
#pragma unroll
        for (int ks = 0; ks < 2; ++ks) {
            uint32_t ah[2][4], al[2][4];
#pragma unroll
            for (int mf = 0; mf < 2; ++mf) {
                uint32_t base = sb + stg + aoff + mf * (16 * KSB) + ks * 32;
                ldm4(ah[mf], base);
                ldm4(al[mf], base + MATB);
            }
#pragma unroll
            for (int p = 0; p < NFP; ++p) {
                uint32_t bb = sb + stg + 2 * MATB + boff + p * (16 * KSB) + ks * 32;
                uint32_t bh[4], bl[4];
                ldm4(bh, bb);
                ldm4(bl, bb + MATB);
#pragma unroll
                for (int mf = 0; mf < 2; ++mf) {
                    mma_bf16(acc[mf][2 * p],     ah[mf], bh[0], bh[1]);
                    mma_bf16(acc[mf][2 * p + 1], ah[mf], bh[2], bh[3]);
                    mma_bf16(acc[mf][2 * p],     ah[mf], bl[0], bl[1]);
                    mma_bf16(acc[mf][2 * p + 1], ah[mf], bl[2], bl[3]);
                    mma_bf16(acc[mf][2 * p],     al[mf], bh[0], bh[1]);
                    mma_bf16(acc[mf][2 * p + 1], al[mf], bh[2], bh[3]);
                }
            }
        }
        if (more) {
            uint32_t nst = (uint32_t)((it + 1) & 1) * STG;
            storeA(nst); storeB(nst);
        }
    }

    /* epilogue */
    const int g2 = lane >> 2, l2 = lane & 3;
#pragma unroll
    for (int mf = 0; mf < 2; ++mf) {
        const int rbase = row0 + m0 + mf * 16 + g2;
#pragma unroll
        for (int nf = 0; nf < 2 * NFP; ++nf) {
            const int gn = col0 + n0 + (nf >> 1) * 16 + (nf & 1) * 8 + l2 * 2;
            float b0 = 0.f, b1 = 0.f;
            if (bias) { b0 = bias[gn]; b1 = bias[gn + 1]; }
            float2 v;
            v.x = acc[mf][nf][0] * scale + b0;
            v.y = acc[mf][nf][1] * scale + b1;
            if (relu) { v.x = fmaxf(v.x, 0.f); v.y = fmaxf(v.y, 0.f); }
            *reinterpret_cast<float2*>(&C[(long long)rbase * ldc + gn]) = v;
            v.x = acc[mf][nf][2] * scale + b0;
            v.y = acc[mf][nf][3] * scale + b1;
            if (relu) { v.x = fmaxf(v.x, 0.f); v.y = fmaxf(v.y, 0.f); }
            *reinterpret_cast<float2*>(&C[(long long)(rbase + 8) * ldc + gn]) = v;
        }
    }
}

/* ---------------- softmax over rows of length SS, in place ---------------- */
__global__ void softmax_kernel(float* __restrict__ attn)
{
    __shared__ float srow[SS];
    __shared__ float red[256];
    const int tid = threadIdx.x;
    float* row = attn + (long long)blockIdx.x * SS;

    float mx = -1e30f;
    for (int j = tid; j < SS; j += 256) {
        float t = row[j];
        srow[j] = t;
        mx = fmaxf(mx, t);
    }
    red[tid] = mx; __syncthreads();
    for (int s = 128; s > 0; s >>= 1) {
        if (tid < s) red[tid] = fmaxf(red[tid], red[tid + s]);
        __syncthreads();
    }
    mx = red[0];
    __syncthreads();

    float sum = 0.f;
    for (int j = tid; j < SS; j += 256) {
        float e = __expf(srow[j] - mx);
        srow[j] = e;
        sum += e;
    }
    red[tid] = sum; __syncthreads();
    for (int s = 128; s > 0; s >>= 1) {
        if (tid < s) red[tid] += red[tid + s];
        __syncthreads();
    }
    const float inv = 1.f / red[0];
    __syncthreads();
    for (int j = tid; j < SS; j += 256) row[j] = srow[j] * inv;
}

/* ------------- out = alpha*(v-mean)/(std+eps)+beta, v = x+y ------------- */
__global__ void add_ln_kernel(const float* __restrict__ x, const float* __restrict__ y,
                              const float* __restrict__ alpha, const float* __restrict__ beta,
                              float* __restrict__ out)
{
    __shared__ float v[D_MODEL];
    __shared__ float red[256];
    const int tid = threadIdx.x;
    const long long base = (long long)blockIdx.x * D_MODEL;

    float s = 0.f;
    for (int j = tid; j < D_MODEL; j += 256) {
        float t = x[base + j] + y[base + j];
        v[j] = t;
        s += t;
    }
    red[tid] = s; __syncthreads();
    for (int st = 128; st > 0; st >>= 1) {
        if (tid < st) red[tid] += red[tid + st];
        __syncthreads();
    }
    const float m = red[0] * (1.f / D_MODEL);
    __syncthreads();

    float c2 = 0.f;
    for (int j = tid; j < D_MODEL; j += 256) {
        float c = v[j] - m;
        c2 += c * c;
    }
    red[tid] = c2; __syncthreads();
    for (int st = 128; st > 0; st >>= 1) {
        if (tid < st) red[tid] += red[tid + st];
        __syncthreads();
    }
    const float stdv = sqrtf(red[0] / (float)(D_MODEL - 1));
    const float inv  = 1.f / (stdv + LN_EPS);
    for (int j = tid; j < D_MODEL; j += 256)
        out[base + j] = alpha[j] * (v[j] - m) * inv + beta[j];
}

/* ---------------- host dispatch ---------------- */
template<int BN_T, bool DIRECT_B>
static void run_mma(const float* A, const float* B, const float* bias, float* C,
                    int M, int N, int K, int lda, int ldb, int ldc,
                    int batch, int HB,
                    long long sA0, long long sA1,
                    long long sB0, long long sB1,
                    long long sC0, long long sC1,
                    float scale, int relu)
{
    cudaFuncSetAttribute((const void*)mma_gemm<BN_T, DIRECT_B>,
                         cudaFuncAttributeMaxDynamicSharedMemorySize, SMEM_TOTAL);
    dim3 grid(N / BN_T, M / 128, batch);
    mma_gemm<BN_T, DIRECT_B><<<grid, 256, SMEM_TOTAL>>>(A, B, bias, C, M, N, K,
                                                        lda, ldb, ldc, HB,
                                                        sA0, sA1, sB0, sB1, sC0, sC1,
                                                        scale, relu);
}

extern "C" void kernel_launch(void* const* d_in, const int* in_sizes, int n_in,
                              void* d_out, int out_size)
{
    const float* x   = (const float*)d_in[0];
    const float* Wq  = (const float*)d_in[1];
    const float* bq  = (const float*)d_in[2];
    const float* Wk  = (const float*)d_in[3];
    const float* bk  = (const float*)d_in[4];
    const float* Wv  = (const float*)d_in[5];
    const float* bv  = (const float*)d_in[6];
    const float* Wo  = (const float*)d_in[7];
    const float* bo  = (const float*)d_in[8];
    const float* W1  = (const float*)d_in[9];
    const float* b1  = (const float*)d_in[10];
    const float* W2  = (const float*)d_in[11];
    const float* b2  = (const float*)d_in[12];
    const float* a1  = (const float*)d_in[13];
    const float* be1 = (const float*)d_in[14];
    const float* a2  = (const float*)d_in[15];
    const float* be2 = (const float*)d_in[16];

    float* out  = (float*)d_out;
    float* enc  = out;                                   /* [B,S,D]   */
    float* attn = out + (size_t)ROWS * D_MODEL;          /* [B,H,S,S] */

    float *Q, *Km, *V, *CTX, *TMP, *AO, *F1, *F2;
    cudaGetSymbolAddress((void**)&Q,   g_Q);
    cudaGetSymbolAddress((void**)&Km,  g_K);
    cudaGetSymbolAddress((void**)&V,   g_V);
    cudaGetSymbolAddress((void**)&CTX, g_ctx);
    cudaGetSymbolAddress((void**)&TMP, g_tmp);
    cudaGetSymbolAddress((void**)&AO,  g_ao);
    cudaGetSymbolAddress((void**)&F1,  g_f1);
    cudaGetSymbolAddress((void**)&F2,  g_f2);

    const long long sBD = (long long)SS * D_MODEL;   /* per-b stride Q/K/V/ctx */
    const long long sSS = (long long)SS * SS;        /* per-head stride attn   */

    /* 1) Q/K/V projections: x[4096,1024] @ W[1024,1024] + b */
    run_mma<128, false>(x, Wq, bq, Q,  ROWS, D_MODEL, D_MODEL, D_MODEL, D_MODEL, D_MODEL,
                        1, 1, 0, 0, 0, 0, 0, 0, 1.f, 0);
    run_mma<128, false>(x, Wk, bk, Km, ROWS, D_MODEL, D_MODEL, D_MODEL, D_MODEL, D_MODEL,
                        1, 1, 0, 0, 0, 0, 0, 0, 1.f, 0);
    run_mma<128, false>(x, Wv, bv, V,  ROWS, D_MODEL, D_MODEL, D_MODEL, D_MODEL, D_MODEL,
                        1, 1, 0, 0, 0, 0, 0, 0, 1.f, 0);

    /* 2) scores = Q K^T / 8 -> attn region (batched b*h); B=[N,K] direct */
    run_mma<128, true>(Q, Km, nullptr, attn, SS, SS, DK, D_MODEL, D_MODEL, SS,
                       BB * N_HEADS, N_HEADS,
                       sBD, DK,
                       sBD, DK,
                       (long long)N_HEADS * sSS, sSS,
                       0.125f, 0);

    /* 3) softmax in place */
    softmax_kernel<<<BB * N_HEADS * SS, 256>>>(attn);

    /* 4) ctx = attn @ V (B=[K,N] transpose-stage), N=64 per head */
    run_mma<64, false>(attn, V, nullptr, CTX, SS, DK, SS, SS, D_MODEL, D_MODEL,
                       BB * N_HEADS, N_HEADS,
                       (long long)N_HEADS * sSS, sSS,
                       sBD, DK,
                       sBD, DK,
                       1.f, 0);

    /* 5) proj = ctx @ Wo + bo */
    run_mma<128, false>(CTX, Wo, bo, TMP, ROWS, D_MODEL, D_MODEL, D_MODEL, D_MODEL, D_MODEL,
                        1, 1, 0, 0, 0, 0, 0, 0, 1.f, 0);

    /* 6) attn_out = LN(x + proj) */
    add_ln_kernel<<<ROWS, 256>>>(x, TMP, a1, be1, AO);

    /* 7) ff1 = relu(attn_out @ W1 + b1) */
    run_mma<128, false>(AO, W1, b1, F1, ROWS, D_FF, D_MODEL, D_MODEL, D_FF, D_FF,
                        1, 1, 0, 0, 0, 0, 0, 0, 1.f, 1);

    /* 8) ff2 = ff1 @ W2 + b2 */
    run_mma<128, false>(F1, W2, b2, F2, ROWS, D_MODEL, D_FF, D_FF, D_MODEL, D_MODEL,
                        1, 1, 0, 0, 0, 0, 0, 0, 1.f, 0);

    /* 9) enc_out = LN(attn_out + ff2) */
    add_ln_kernel<<<ROWS, 256>>>(AO, F2, a2, be2, enc);

    (void)in_sizes; (void)n_in; (void)out_size;
}

// round 4
// speedup vs baseline: 2.3521x; 1.8755x over previous
#include <cuda_runtime.h>
#include <cuda_bf16.h>
#include <math.h>
#include <stdint.h>

#define D_MODEL 1024
#define N_HEADS 16
#define D_FF    4096
#define BB      2
#define SS      2048
#define DK      64
#define ROWS    (BB*SS)          /* 4096 */
#define LN_EPS  1e-6f

typedef __nv_bfloat16 bf16;
typedef __nv_bfloat162 bf162;

/* ---------------- scratch (no allocations allowed) ---------------- */
__device__ float g_tmp[ROWS*D_MODEL];
__device__ float g_ao [ROWS*D_MODEL];
__device__ float g_f2 [ROWS*D_MODEL];

__device__ bf16 g_xhi[ROWS*D_MODEL],  g_xlo[ROWS*D_MODEL];
__device__ bf16 g_wqhi[D_MODEL*D_MODEL], g_wqlo[D_MODEL*D_MODEL];
__device__ bf16 g_wkhi[D_MODEL*D_MODEL], g_wklo[D_MODEL*D_MODEL];
__device__ bf16 g_wvhi[D_MODEL*D_MODEL], g_wvlo[D_MODEL*D_MODEL];
__device__ bf16 g_wohi[D_MODEL*D_MODEL], g_wolo[D_MODEL*D_MODEL];
__device__ bf16 g_w1hi[(size_t)D_MODEL*D_FF], g_w1lo[(size_t)D_MODEL*D_FF];
__device__ bf16 g_w2hi[(size_t)D_MODEL*D_FF], g_w2lo[(size_t)D_MODEL*D_FF];
__device__ bf16 g_qhi[ROWS*D_MODEL],  g_qlo[ROWS*D_MODEL];
__device__ bf16 g_khi[ROWS*D_MODEL],  g_klo[ROWS*D_MODEL];
__device__ bf16 g_vthi[ROWS*D_MODEL], g_vtlo[ROWS*D_MODEL];
__device__ bf16 g_phi[(size_t)BB*N_HEADS*SS*SS], g_plo[(size_t)BB*N_HEADS*SS*SS];
__device__ bf16 g_chi[ROWS*D_MODEL],  g_clo[ROWS*D_MODEL];
__device__ bf16 g_aohi[ROWS*D_MODEL], g_aolo[ROWS*D_MODEL];
__device__ bf16 g_f1hi[(size_t)ROWS*D_FF], g_f1lo[(size_t)ROWS*D_FF];

/* ---------------- helpers ---------------- */
__device__ __forceinline__ uint32_t smem_u32(const void* p) {
    uint32_t a;
    asm("{ .reg .u64 t; cvta.to.shared.u64 t, %1; cvt.u32.u64 %0, t; }" : "=r"(a) : "l"(p));
    return a;
}
__device__ __forceinline__ void ldm4(uint32_t* d, uint32_t addr) {
    asm volatile("ldmatrix.sync.aligned.m8n8.x4.shared.b16 {%0,%1,%2,%3}, [%4];"
                 : "=r"(d[0]), "=r"(d[1]), "=r"(d[2]), "=r"(d[3]) : "r"(addr));
}
__device__ __forceinline__ void mma_bf16(float* c, const uint32_t* a, uint32_t b0, uint32_t b1) {
    asm volatile("mma.sync.aligned.m16n8k16.row.col.f32.bf16.bf16.f32 "
                 "{%0,%1,%2,%3}, {%4,%5,%6,%7}, {%8,%9}, {%0,%1,%2,%3};"
                 : "+f"(c[0]), "+f"(c[1]), "+f"(c[2]), "+f"(c[3])
                 : "r"(a[0]), "r"(a[1]), "r"(a[2]), "r"(a[3]), "r"(b0), "r"(b1));
}
#define CP16(dst, src) asm volatile("cp.async.cg.shared.global [%0], [%1], 16;" :: "r"(dst), "l"(src))
#define CPCOMMIT()     asm volatile("cp.async.commit_group;" ::: "memory")
#define CPWAIT(n)      asm volatile("cp.async.wait_group %0;" :: "n"(n) : "memory")

__device__ __forceinline__ void split2_store(float a, float b, bf16* hi, bf16* lo) {
    bf162 h = __floats2bfloat162_rn(a, b);
    float2 f = __bfloat1622float2(h);
    bf162 l = __floats2bfloat162_rn(a - f.x, b - f.y);
    *reinterpret_cast<bf162*>(hi) = h;
    *reinterpret_cast<bf162*>(lo) = l;
}

/* ================= bf16 hi/lo GEMM (mma.sync) =================
 * C[M,N] = scale*(A @ B^T) + bias (+relu), all operands pre-split bf16
 * A: hi/lo [M,K] row-major (lda). B: hi/lo [N,K] row-major (ldb).
 * 3 passes: ah*bh + ah*bl + al*bh -> fp32 acc.
 * Tile 128 x BN_T x 32, 8 warps (4m x 2n), 2-stage cp.async pipeline.
 * OUTM: 0 = fp32 C, 1 = bf16 hi/lo C.
 */
#define KSB   80                  /* smem row stride bytes (32 bf16 + pad) */
#define HMAT  (128*KSB)           /* 10240 per matrix half */
#define STG   (4*HMAT)            /* 40960 per stage */
#define SMEM_TOTAL (2*STG)        /* 81920 */

template<int BN_T, int OUTM, bool BIAS_ROW, bool RELU>
__global__ void __launch_bounds__(256, 2)
gemm_bf(const bf16* __restrict__ Ahi, const bf16* __restrict__ Alo,
        const bf16* __restrict__ Bhi, const bf16* __restrict__ Blo,
        const float* __restrict__ bias,
        float* __restrict__ Cf, bf16* __restrict__ Chi, bf16* __restrict__ Clo,
        int K, int lda, int ldb, int ldc, int HB,
        long long sA0, long long sA1, long long sB0, long long sB1,
        long long sC0, long long sC1, float scale)
{
    extern __shared__ char smem[];
    const uint32_t sb = smem_u32(smem);
    const int tid = threadIdx.x, lane = tid & 31, wid = tid >> 5;

    const int z = blockIdx.z;
    const long long oA = (long long)(z / HB) * sA0 + (long long)(z % HB) * sA1;
    const long long oB = (long long)(z / HB) * sB0 + (long long)(z % HB) * sB1;
    const long long oC = (long long)(z / HB) * sC0 + (long long)(z % HB) * sC1;
    Ahi += oA; Alo += oA; Bhi += oB; Blo += oB;

    const int row0 = blockIdx.y * 128, col0 = blockIdx.x * BN_T;
    constexpr int NFP = BN_T / 32;
    const int wm = wid & 3, wn = wid >> 2;
    const int m0 = wm * 32, n0 = wn * (BN_T / 2);

    const int r8 = lane & 7, sel = lane >> 3;
    const uint32_t aoff = (uint32_t)(m0 + (sel & 1) * 8 + r8) * KSB + (uint32_t)((sel >> 1) * 8) * 2u;
    const uint32_t boff = (uint32_t)(n0 + (sel >> 1) * 8 + r8) * KSB + (uint32_t)((sel & 1) * 8) * 2u;

    float acc[2][2 * NFP][4];
#pragma unroll
    for (int i = 0; i < 2; i++)
#pragma unroll
        for (int j = 0; j < 2 * NFP; j++)
#pragma unroll
            for (int q = 0; q < 4; q++) acc[i][j][q] = 0.f;

    const int NCH = K >> 5;

    auto issue = [&](int it) {
        const int k0 = it * 32;
        const uint32_t s = sb + (uint32_t)(it & 1) * STG;
#pragma unroll
        for (int i = 0; i < 2; i++) {
            int e = tid + i * 256, r = e >> 2, c = e & 3;
            uint32_t d = s + (uint32_t)(r * KSB + c * 16);
            const long long go = (long long)(row0 + r) * lda + k0 + c * 8;
            CP16(d,        Ahi + go);
            CP16(d + HMAT, Alo + go);
        }
#pragma unroll
        for (int i = 0; i < BN_T / 64; i++) {
            int e = tid + i * 256, r = e >> 2, c = e & 3;
            uint32_t d = s + 2 * HMAT + (uint32_t)(r * KSB + c * 16);
            const long long go = (long long)(col0 + r) * ldb + k0 + c * 8;
            CP16(d,        Bhi + go);
            CP16(d + HMAT, Blo + go);
        }
        CPCOMMIT();
    };

    issue(0);
    for (int it = 0; it < NCH; ++it) {
        if (it + 1 < NCH) {
            __syncthreads();          /* buffer (it+1)&1 free: compute it-1 done */
            issue(it + 1);
            CPWAIT(1);
        } else {
            CPWAIT(0);
        }
        __syncthreads();

        const uint32_t stg = sb + (uint32_t)(it & 1) * STG;
#pragma unroll
        for (int ks = 0; ks < 2; ++ks) {
            uint32_t ah[2][4], al[2][4];
#pragma unroll
            for (int mf = 0; mf < 2; ++mf) {
                uint32_t base = stg + aoff + mf * (16 * KSB) + ks * 32;
                ldm4(ah[mf], base);
                ldm4(al[mf], base + HMAT);
            }
#pragma unroll
            for (int p = 0; p < NFP; ++p) {
                uint32_t bb = stg + 2 * HMAT + boff + p * (16 * KSB) + ks * 32;
                uint32_t bh[4], bl[4];
                ldm4(bh, bb);
                ldm4(bl, bb + HMAT);
#pragma unroll
                for (int mf = 0; mf < 2; ++mf) {
                    mma_bf16(acc[mf][2 * p],     ah[mf], bh[0], bh[1]);
                    mma_bf16(acc[mf][2 * p + 1], ah[mf], bh[2], bh[3]);
                    mma_bf16(acc[mf][2 * p],     ah[mf], bl[0], bl[1]);
                    mma_bf16(acc[mf][2 * p + 1], ah[mf], bl[2], bl[3]);
                    mma_bf16(acc[mf][2 * p],     al[mf], bh[0], bh[1]);
                    mma_bf16(acc[mf][2 * p + 1], al[mf], bh[2], bh[3]);
                }
            }
        }
    }

    /* epilogue */
    const int g2 = lane >> 2, l2 = lane & 3;
#pragma unroll
    for (int mf = 0; mf < 2; ++mf) {
        const int rg = row0 + m0 + mf * 16 + g2;
#pragma unroll
        for (int nf = 0; nf < 2 * NFP; ++nf) {
            const int gn = col0 + n0 + (nf >> 1) * 16 + (nf & 1) * 8 + l2 * 2;
            float c0 = acc[mf][nf][0] * scale, c1 = acc[mf][nf][1] * scale;
            float c2 = acc[mf][nf][2] * scale, c3 = acc[mf][nf][3] * scale;
            if (bias) {
                if (BIAS_ROW) {
                    float b0 = bias[rg], b8 = bias[rg + 8];
                    c0 += b0; c1 += b0; c2 += b8; c3 += b8;
                } else {
                    float b0 = bias[gn], b1 = bias[gn + 1];
                    c0 += b0; c1 += b1; c2 += b0; c3 += b1;
                }
            }
            if (RELU) {
                c0 = fmaxf(c0, 0.f); c1 = fmaxf(c1, 0.f);
                c2 = fmaxf(c2, 0.f); c3 = fmaxf(c3, 0.f);
            }
            const long long i0 = oC + (long long)rg * ldc + gn;
            const long long i8 = oC + (long long)(rg + 8) * ldc + gn;
            if (OUTM == 0) {
                *reinterpret_cast<float2*>(&Cf[i0]) = make_float2(c0, c1);
                *reinterpret_cast<float2*>(&Cf[i8]) = make_float2(c2, c3);
            } else {
                split2_store(c0, c1, &Chi[i0], &Clo[i0]);
                split2_store(c2, c3, &Chi[i8], &Clo[i8]);
            }
        }
    }
}

/* ---------- fp32 -> bf16 hi/lo (plain) ---------- */
__global__ void split_kernel(const float* __restrict__ in, bf16* __restrict__ hi,
                             bf16* __restrict__ lo, int n4)
{
    int i = blockIdx.x * 256 + threadIdx.x;
    if (i >= n4) return;
    float4 v = reinterpret_cast<const float4*>(in)[i];
    bf162 h01 = __floats2bfloat162_rn(v.x, v.y);
    bf162 h23 = __floats2bfloat162_rn(v.z, v.w);
    float2 f01 = __bfloat1622float2(h01);
    float2 f23 = __bfloat1622float2(h23);
    bf162 l01 = __floats2bfloat162_rn(v.x - f01.x, v.y - f01.y);
    bf162 l23 = __floats2bfloat162_rn(v.z - f23.x, v.w - f23.y);
    reinterpret_cast<bf162*>(hi)[i * 2]     = h01;
    reinterpret_cast<bf162*>(hi)[i * 2 + 1] = h23;
    reinterpret_cast<bf162*>(lo)[i * 2]     = l01;
    reinterpret_cast<bf162*>(lo)[i * 2 + 1] = l23;
}

/* ---------- W[Kdim,Ndim] -> Wt hi/lo [Ndim,Kdim] (transpose + split) ---------- */
__global__ void splitT_kernel(const float* __restrict__ W, bf16* __restrict__ thi,
                              bf16* __restrict__ tlo, int Kdim, int Ndim)
{
    __shared__ float t[32][33];
    const int n0 = blockIdx.x * 32, k0 = blockIdx.y * 32;
    const int tx = threadIdx.x, ty = threadIdx.y;
#pragma unroll
    for (int i = 0; i < 32; i += 8)
        t[ty + i][tx] = W[(long long)(k0 + ty + i) * Ndim + n0 + tx];
    __syncthreads();
#pragma unroll
    for (int i = 0; i < 32; i += 8) {
        float v = t[tx][ty + i];
        bf16 h = __float2bfloat16(v);
        bf16 l = __float2bfloat16(v - __bfloat162float(h));
        long long o = (long long)(n0 + ty + i) * Kdim + k0 + tx;
        thi[o] = h; tlo[o] = l;
    }
}

/* ---------------- softmax over rows of SS, in place + bf16 hi/lo ---------------- */
__global__ void softmax_kernel(float* __restrict__ attn, bf16* __restrict__ phi,
                               bf16* __restrict__ plo)
{
    __shared__ float srow[SS];
    __shared__ float red[256];
    const int tid = threadIdx.x;
    const long long rb = (long long)blockIdx.x * SS;
    float* row = attn + rb;

    float mx = -1e30f;
    for (int j = tid; j < SS; j += 256) {
        float t = row[j];
        srow[j] = t;
        mx = fmaxf(mx, t);
    }
    red[tid] = mx; __syncthreads();
    for (int s = 128; s > 0; s >>= 1) {
        if (tid < s) red[tid] = fmaxf(red[tid], red[tid + s]);
        __syncthreads();
    }
    mx = red[0];
    __syncthreads();

    float sum = 0.f;
    for (int j = tid; j < SS; j += 256) {
        float e = __expf(srow[j] - mx);
        srow[j] = e;
        sum += e;
    }
    red[tid] = sum; __syncthreads();
    for (int s = 128; s > 0; s >>= 1) {
        if (tid < s) red[tid] += red[tid + s];
        __syncthreads();
    }
    const float inv = 1.f / red[0];
    __syncthreads();
    for (int j = tid * 2; j < SS; j += 512) {
        float e0 = srow[j] * inv, e1 = srow[j + 1] * inv;
        *reinterpret_cast<float2*>(&row[j]) = make_float2(e0, e1);
        split2_store(e0, e1, phi + rb + j, plo + rb + j);
    }
}

/* ------------- out = alpha*(v-mean)/(std+eps)+beta, v = x+y (+bf16 hi/lo) ------ */
__global__ void add_ln_kernel(const float* __restrict__ x, const float* __restrict__ y,
                              const float* __restrict__ alpha, const float* __restrict__ beta,
                              float* __restrict__ out, bf16* __restrict__ ohi,
                              bf16* __restrict__ olo)
{
    __shared__ float v[D_MODEL];
    __shared__ float red[256];
    const int tid = threadIdx.x;
    const long long base = (long long)blockIdx.x * D_MODEL;

    float s = 0.f;
    for (int j = tid; j < D_MODEL; j += 256) {
        float t = x[base + j] + y[base + j];
        v[j] = t;
        s += t;
    }
    red[tid] = s; __syncthreads();
    for (int st = 128; st > 0; st >>= 1) {
        if (tid < st) red[tid] += red[tid + st];
        __syncthreads();
    }
    const float m = red[0] * (1.f / D_MODEL);
    __syncthreads();

    float c2 = 0.f;
    for (int j = tid; j < D_MODEL; j += 256) {
        float c = v[j] - m;
        c2 += c * c;
    }
    red[tid] = c2; __syncthreads();
    for (int st = 128; st > 0; st >>= 1) {
        if (tid < st) red[tid] += red[tid + st];
        __syncthreads();
    }
    const float stdv = sqrtf(red[0] / (float)(D_MODEL - 1));
    const float inv  = 1.f / (stdv + LN_EPS);
    for (int j = tid * 2; j < D_MODEL; j += 512) {
        float o0 = alpha[j] * (v[j] - m) * inv + beta[j];
        float o1 = alpha[j + 1] * (v[j + 1] - m) * inv + beta[j + 1];
        *reinterpret_cast<float2*>(&out[base + j]) = make_float2(o0, o1);
        if (ohi) split2_store(o0, o1, ohi + base + j, olo + base + j);
    }
}

/* ---------------- host dispatch ---------------- */
template<int BN_T, int OUTM, bool BIAS_ROW, bool RELU>
static void run_g(const bf16* Ahi, const bf16* Alo, const bf16* Bhi, const bf16* Blo,
                  const float* bias, float* Cf, bf16* Chi, bf16* Clo,
                  int M, int N, int K, int lda, int ldb, int ldc,
                  int batch, int HB,
                  long long sA0, long long sA1, long long sB0, long long sB1,
                  long long sC0, long long sC1, float scale)
{
    cudaFuncSetAttribute((const void*)gemm_bf<BN_T, OUTM, BIAS_ROW, RELU>,
                         cudaFuncAttributeMaxDynamicSharedMemorySize, SMEM_TOTAL);
    dim3 grid(N / BN_T, M / 128, batch);
    gemm_bf<BN_T, OUTM, BIAS_ROW, RELU><<<grid, 256, SMEM_TOTAL>>>(
        Ahi, Alo, Bhi, Blo, bias, Cf, Chi, Clo, K, lda, ldb, ldc,
        HB, sA0, sA1, sB0, sB1, sC0, sC1, scale);
}

#define GETSYM(var, sym) cudaGetSymbolAddress((void**)&var, sym)

extern "C" void kernel_launch(void* const* d_in, const int* in_sizes, int n_in,
                              void* d_out, int out_size)
{
    const float* x   = (const float*)d_in[0];
    const float* Wq  = (const float*)d_in[1];
    const float* bq  = (const float*)d_in[2];
    const float* Wk  = (const float*)d_in[3];
    const float* bk  = (const float*)d_in[4];
    const float* Wv  = (const float*)d_in[5];
    const float* bv  = (const float*)d_in[6];
    const float* Wo  = (const float*)d_in[7];
    const float* bo  = (const float*)d_in[8];
    const float* W1  = (const float*)d_in[9];
    const float* b1  = (const float*)d_in[10];
    const float* W2  = (const float*)d_in[11];
    const float* b2  = (const float*)d_in[12];
    const float* a1  = (const float*)d_in[13];
    const float* be1 = (const float*)d_in[14];
    const float* a2  = (const float*)d_in[15];
    const float* be2 = (const float*)d_in[16];

    float* out  = (float*)d_out;
    float* enc  = out;                                   /* [B,S,D]   */
    float* attn = out + (size_t)ROWS * D_MODEL;          /* [B,H,S,S] */

    float *TMP, *AO, *F2;
    GETSYM(TMP, g_tmp); GETSYM(AO, g_ao); GETSYM(F2, g_f2);
    bf16 *xhi, *xlo, *wqhi, *wqlo, *wkhi, *wklo, *wvhi, *wvlo, *wohi, *wolo;
    bf16 *w1hi, *w1lo, *w2hi, *w2lo, *qhi, *qlo, *khi, *klo, *vthi, *vtlo;
    bf16 *phi, *plo, *chi, *clo, *aohi, *aolo, *f1hi, *f1lo;
    GETSYM(xhi, g_xhi);  GETSYM(xlo, g_xlo);
    GETSYM(wqhi, g_wqhi); GETSYM(wqlo, g_wqlo);
    GETSYM(wkhi, g_wkhi); GETSYM(wklo, g_wklo);
    GETSYM(wvhi, g_wvhi); GETSYM(wvlo, g_wvlo);
    GETSYM(wohi, g_wohi); GETSYM(wolo, g_wolo);
    GETSYM(w1hi, g_w1hi); GETSYM(w1lo, g_w1lo);
    GETSYM(w2hi, g_w2hi); GETSYM(w2lo, g_w2lo);
    GETSYM(qhi, g_qhi);   GETSYM(qlo, g_qlo);
    GETSYM(khi, g_khi);   GETSYM(klo, g_klo);
    GETSYM(vthi, g_vthi); GETSYM(vtlo, g_vtlo);
    GETSYM(phi, g_phi);   GETSYM(plo, g_plo);
    GETSYM(chi, g_chi);   GETSYM(clo, g_clo);
    GETSYM(aohi, g_aohi); GETSYM(aolo, g_aolo);
    GETSYM(f1hi, g_f1hi); GETSYM(f1lo, g_f1lo);

    const long long sBD = (long long)SS * D_MODEL;   /* per-b stride in row-major acts */
    const long long sSS = (long long)SS * SS;        /* per-head stride in attn/P      */

    /* 0) conversions */
    split_kernel<<<(ROWS * D_MODEL / 4 + 255) / 256, 256>>>(x, xhi, xlo, ROWS * D_MODEL / 4);
    dim3 tb(32, 8);
    splitT_kernel<<<dim3(D_MODEL / 32, D_MODEL / 32), tb>>>(Wq, wqhi, wqlo, D_MODEL, D_MODEL);
    splitT_kernel<<<dim3(D_MODEL / 32, D_MODEL / 32), tb>>>(Wk, wkhi, wklo, D_MODEL, D_MODEL);
    splitT_kernel<<<dim3(D_MODEL / 32, D_MODEL / 32), tb>>>(Wv, wvhi, wvlo, D_MODEL, D_MODEL);
    splitT_kernel<<<dim3(D_MODEL / 32, D_MODEL / 32), tb>>>(Wo, wohi, wolo, D_MODEL, D_MODEL);
    splitT_kernel<<<dim3(D_FF / 32, D_MODEL / 32),    tb>>>(W1, w1hi, w1lo, D_MODEL, D_FF);
    splitT_kernel<<<dim3(D_MODEL / 32, D_FF / 32),    tb>>>(W2, w2hi, w2lo, D_FF, D_MODEL);

    /* 1) Q, K: [4096,1024] = x @ Wq^T^T, bf16 out */
    run_g<128, 1, false, false>(xhi, xlo, wqhi, wqlo, bq, nullptr, qhi, qlo,
                                ROWS, D_MODEL, D_MODEL, D_MODEL, D_MODEL, D_MODEL,
                                1, 1, 0, 0, 0, 0, 0, 0, 1.f);
    run_g<128, 1, false, false>(xhi, xlo, wkhi, wklo, bk, nullptr, khi, klo,
                                ROWS, D_MODEL, D_MODEL, D_MODEL, D_MODEL, D_MODEL,
                                1, 1, 0, 0, 0, 0, 0, 0, 1.f);
    /* Vt = Wv^T @ x^T: [1024, 4096], row-bias bv, bf16 out */
    run_g<128, 1, true, false>(wvhi, wvlo, xhi, xlo, bv, nullptr, vthi, vtlo,
                               D_MODEL, ROWS, D_MODEL, D_MODEL, D_MODEL, ROWS,
                               1, 1, 0, 0, 0, 0, 0, 0, 1.f);

    /* 2) scores = Q K^T / 8 -> attn (fp32), batched over b*h */
    run_g<128, 0, false, false>(qhi, qlo, khi, klo, nullptr, attn, nullptr, nullptr,
                                SS, SS, DK, D_MODEL, D_MODEL, SS,
                                BB * N_HEADS, N_HEADS,
                                sBD, DK, sBD, DK,
                                (long long)N_HEADS * sSS, sSS, 0.125f);

    /* 3) softmax in place + P hi/lo */
    softmax_kernel<<<BB * N_HEADS * SS, 256>>>(attn, phi, plo);

    /* 4) ctx = P @ V: A = P [S,S], B = Vt [64, 4096-cols], C -> ctx hi/lo */
    run_g<64, 1, false, false>(phi, plo, vthi, vtlo, nullptr, nullptr, chi, clo,
                               SS, DK, SS, SS, ROWS, D_MODEL,
                               BB * N_HEADS, N_HEADS,
                               (long long)N_HEADS * sSS, sSS,
                               (long long)SS, (long long)DK * ROWS,
                               sBD, DK, 1.f);

    /* 5) proj = ctx @ Wo^T^T + bo -> TMP (fp32) */
    run_g<128, 0, false, false>(chi, clo, wohi, wolo, bo, TMP, nullptr, nullptr,
                                ROWS, D_MODEL, D_MODEL, D_MODEL, D_MODEL, D_MODEL,
                                1, 1, 0, 0, 0, 0, 0, 0, 1.f);

    /* 6) attn_out = LN(x + proj) -> AO fp32 + hi/lo */
    add_ln_kernel<<<ROWS, 256>>>(x, TMP, a1, be1, AO, aohi, aolo);

    /* 7) ff1 = relu(AO @ W1 + b1) -> F1 hi/lo */
    run_g<128, 1, false, true>(aohi, aolo, w1hi, w1lo, b1, nullptr, f1hi, f1lo,
                               ROWS, D_FF, D_MODEL, D_MODEL, D_MODEL, D_FF,
                               1, 1, 0, 0, 0, 0, 0, 0, 1.f);

    /* 8) ff2 = F1 @ W2 + b2 -> F2 fp32 */
    run_g<128, 0, false, false>(f1hi, f1lo, w2hi, w2lo, b2, F2, nullptr, nullptr,
                                ROWS, D_MODEL, D_FF, D_FF, D_FF, D_MODEL,
                                1, 1, 0, 0, 0, 0, 0, 0, 1.f);

    /* 9) enc_out = LN(AO + F2) */
    add_ln_kernel<<<ROWS, 256>>>(AO, F2, a2, be2, enc, nullptr, nullptr);

    (void)in_sizes; (void)n_in; (void)out_size;
}

// round 6
// speedup vs baseline: 2.8182x; 1.1982x over previous
#include <cuda_runtime.h>
#include <cuda_bf16.h>
#include <math.h>
#include <stdint.h>

#define D_MODEL 1024
#define N_HEADS 16
#define D_FF    4096
#define BB      2
#define SS      2048
#define DK      64
#define ROWS    (BB*SS)          /* 4096 */
#define LN_EPS  1e-6f

typedef __nv_bfloat16 bf16;
typedef __nv_bfloat162 bf162;

/* ---------------- scratch (no allocations allowed) ---------------- */
__device__ float g_tmp[ROWS*D_MODEL];
__device__ float g_ao [ROWS*D_MODEL];
__device__ float g_f2 [ROWS*D_MODEL];
__device__ float g_rowsum[(size_t)BB*N_HEADS*SS];

__device__ bf16 g_xhi[ROWS*D_MODEL],  g_xlo[ROWS*D_MODEL];
__device__ bf16 g_wqhi[D_MODEL*D_MODEL], g_wqlo[D_MODEL*D_MODEL];
__device__ bf16 g_wkhi[D_MODEL*D_MODEL], g_wklo[D_MODEL*D_MODEL];
__device__ bf16 g_wvhi[D_MODEL*D_MODEL], g_wvlo[D_MODEL*D_MODEL];
__device__ bf16 g_wohi[D_MODEL*D_MODEL], g_wolo[D_MODEL*D_MODEL];
__device__ bf16 g_w1hi[(size_t)D_MODEL*D_FF], g_w1lo[(size_t)D_MODEL*D_FF];
__device__ bf16 g_w2hi[(size_t)D_MODEL*D_FF], g_w2lo[(size_t)D_MODEL*D_FF];
__device__ bf16 g_qhi[ROWS*D_MODEL],  g_qlo[ROWS*D_MODEL];
__device__ bf16 g_khi[ROWS*D_MODEL],  g_klo[ROWS*D_MODEL];
__device__ bf16 g_vthi[ROWS*D_MODEL], g_vtlo[ROWS*D_MODEL];
__device__ bf16 g_chi[ROWS*D_MODEL],  g_clo[ROWS*D_MODEL];
__device__ bf16 g_aohi[ROWS*D_MODEL], g_aolo[ROWS*D_MODEL];
__device__ bf16 g_f1hi[(size_t)ROWS*D_FF], g_f1lo[(size_t)ROWS*D_FF];

/* ---------------- helpers ---------------- */
__device__ __forceinline__ uint32_t smem_u32(const void* p) {
    uint32_t a;
    asm("{ .reg .u64 t; cvta.to.shared.u64 t, %1; cvt.u32.u64 %0, t; }" : "=r"(a) : "l"(p));
    return a;
}
__device__ __forceinline__ void ldm4(uint32_t* d, uint32_t addr) {
    asm volatile("ldmatrix.sync.aligned.m8n8.x4.shared.b16 {%0,%1,%2,%3}, [%4];"
                 : "=r"(d[0]), "=r"(d[1]), "=r"(d[2]), "=r"(d[3]) : "r"(addr));
}
__device__ __forceinline__ void mma_bf16(float* c, const uint32_t* a, uint32_t b0, uint32_t b1) {
    asm volatile("mma.sync.aligned.m16n8k16.row.col.f32.bf16.bf16.f32 "
                 "{%0,%1,%2,%3}, {%4,%5,%6,%7}, {%8,%9}, {%0,%1,%2,%3};"
                 : "+f"(c[0]), "+f"(c[1]), "+f"(c[2]), "+f"(c[3])
                 : "r"(a[0]), "r"(a[1]), "r"(a[2]), "r"(a[3]), "r"(b0), "r"(b1));
}
#define CP16(dst, src) asm volatile("cp.async.cg.shared.global [%0], [%1], 16;" :: "r"(dst), "l"(src))
#define CPCOMMIT()     asm volatile("cp.async.commit_group;" ::: "memory")
#define CPWAIT(n)      asm volatile("cp.async.wait_group %0;" :: "n"(n) : "memory")

__device__ __forceinline__ void split2_store(float a, float b, bf16* hi, bf16* lo) {
    bf162 h = __floats2bfloat162_rn(a, b);
    float2 f = __bfloat1622float2(h);
    bf162 l = __floats2bfloat162_rn(a - f.x, b - f.y);
    *reinterpret_cast<bf162*>(hi) = h;
    *reinterpret_cast<bf162*>(lo) = l;
}
__device__ __forceinline__ void split4r(float4 v, uint2& hi, uint2& lo) {
    bf162 h01 = __floats2bfloat162_rn(v.x, v.y);
    bf162 h23 = __floats2bfloat162_rn(v.z, v.w);
    float2 f01 = __bfloat1622float2(h01);
    float2 f23 = __bfloat1622float2(h23);
    bf162 l01 = __floats2bfloat162_rn(v.x - f01.x, v.y - f01.y);
    bf162 l23 = __floats2bfloat162_rn(v.z - f23.x, v.w - f23.y);
    hi.x = *reinterpret_cast<uint32_t*>(&h01);
    hi.y = *reinterpret_cast<uint32_t*>(&h23);
    lo.x = *reinterpret_cast<uint32_t*>(&l01);
    lo.y = *reinterpret_cast<uint32_t*>(&l23);
}

/* ================= bf16 hi/lo GEMM (mma.sync) =================
 * OUTM: 0 = fp32 C; 1 = bf16 hi/lo C; 2 = exp(scale*acc) fp32 C + rowsum atomics.
 */
#define KSB   80
#define HMAT  (128*KSB)           /* 10240 per matrix half */
#define STG   (4*HMAT)            /* 40960 per stage */
#define SMEM_TOTAL (2*STG)        /* 81920 */

template<int BN_T, int OUTM, bool BIAS_ROW, bool RELU>
__global__ void __launch_bounds__(256, 2)
gemm_bf(const bf16* __restrict__ Ahi, const bf16* __restrict__ Alo,
        const bf16* __restrict__ Bhi, const bf16* __restrict__ Blo,
        const float* __restrict__ bias,
        float* __restrict__ Cf, bf16* __restrict__ Chi, bf16* __restrict__ Clo,
        float* __restrict__ rowsum,
        int K, int lda, int ldb, int ldc, int HB,
        long long sA0, long long sA1, long long sB0, long long sB1,
        long long sC0, long long sC1, float scale)
{
    extern __shared__ char smem[];
    const uint32_t sb = smem_u32(smem);
    const int tid = threadIdx.x, lane = tid & 31, wid = tid >> 5;

    const int z = blockIdx.z;
    const long long oA = (long long)(z / HB) * sA0 + (long long)(z % HB) * sA1;
    const long long oB = (long long)(z / HB) * sB0 + (long long)(z % HB) * sB1;
    const long long oC = (long long)(z / HB) * sC0 + (long long)(z % HB) * sC1;
    Ahi += oA; Alo += oA; Bhi += oB; Blo += oB;

    const int row0 = blockIdx.y * 128, col0 = blockIdx.x * BN_T;
    constexpr int NFP = BN_T / 32;
    const int wm = wid & 3, wn = wid >> 2;
    const int m0 = wm * 32, n0 = wn * (BN_T / 2);

    const int r8 = lane & 7, sel = lane >> 3;
    const uint32_t aoff = (uint32_t)(m0 + (sel & 1) * 8 + r8) * KSB + (uint32_t)((sel >> 1) * 8) * 2u;
    const uint32_t boff = (uint32_t)(n0 + (sel >> 1) * 8 + r8) * KSB + (uint32_t)((sel & 1) * 8) * 2u;

    float acc[2][2 * NFP][4];
#pragma unroll
    for (int i = 0; i < 2; i++)
#pragma unroll
        for (int j = 0; j < 2 * NFP; j++)
#pragma unroll
            for (int q = 0; q < 4; q++) acc[i][j][q] = 0.f;

    const int NCH = K >> 5;

    auto issue = [&](int it) {
        const int k0 = it * 32;
        const uint32_t s = sb + (uint32_t)(it & 1) * STG;
#pragma unroll
        for (int i = 0; i < 2; i++) {
            int e = tid + i * 256, r = e >> 2, c = e & 3;
            uint32_t d = s + (uint32_t)(r * KSB + c * 16);
            const long long go = (long long)(row0 + r) * lda + k0 + c * 8;
            CP16(d,        Ahi + go);
            CP16(d + HMAT, Alo + go);
        }
#pragma unroll
        for (int i = 0; i < BN_T / 64; i++) {
            int e = tid + i * 256, r = e >> 2, c = e & 3;
            uint32_t d = s + 2 * HMAT + (uint32_t)(r * KSB + c * 16);
            const long long go = (long long)(col0 + r) * ldb + k0 + c * 8;
            CP16(d,        Bhi + go);
            CP16(d + HMAT, Blo + go);
        }
        CPCOMMIT();
    };

    issue(0);
    for (int it = 0; it < NCH; ++it) {
        if (it + 1 < NCH) {
            __syncthreads();
            issue(it + 1);
            CPWAIT(1);
        } else {
            CPWAIT(0);
        }
        __syncthreads();

        const uint32_t stg = sb + (uint32_t)(it & 1) * STG;
#pragma unroll
        for (int ks = 0; ks < 2; ++ks) {
            uint32_t ah[2][4], al[2][4];
#pragma unroll
            for (int mf = 0; mf < 2; ++mf) {
                uint32_t base = stg + aoff + mf * (16 * KSB) + ks * 32;
                ldm4(ah[mf], base);
                ldm4(al[mf], base + HMAT);
            }
#pragma unroll
            for (int p = 0; p < NFP; ++p) {
                uint32_t bb = stg + 2 * HMAT + boff + p * (16 * KSB) + ks * 32;
                uint32_t bh[4], bl[4];
                ldm4(bh, bb);
                ldm4(bl, bb + HMAT);
#pragma unroll
                for (int mf = 0; mf < 2; ++mf) {
                    mma_bf16(acc[mf][2 * p],     ah[mf], bh[0], bh[1]);
                    mma_bf16(acc[mf][2 * p + 1], ah[mf], bh[2], bh[3]);
                    mma_bf16(acc[mf][2 * p],     ah[mf], bl[0], bl[1]);
                    mma_bf16(acc[mf][2 * p + 1], ah[mf], bl[2], bl[3]);
                    mma_bf16(acc[mf][2 * p],     al[mf], bh[0], bh[1]);
                    mma_bf16(acc[mf][2 * p + 1], al[mf], bh[2], bh[3]);
                }
            }
        }
    }

    /* epilogue */
    float* rs = reinterpret_cast<float*>(smem);
    if (OUTM == 2) {
        __syncthreads();
        if (tid < 128) rs[tid] = 0.f;
        __syncthreads();
    }

    const int g2 = lane >> 2, l2 = lane & 3;
#pragma unroll
    for (int mf = 0; mf < 2; ++mf) {
        const int lr = m0 + mf * 16 + g2;
        const int rg = row0 + lr;
        float p0 = 0.f, p8 = 0.f;
#pragma unroll
        for (int nf = 0; nf < 2 * NFP; ++nf) {
            const int gn = col0 + n0 + (nf >> 1) * 16 + (nf & 1) * 8 + l2 * 2;
            float c0 = acc[mf][nf][0] * scale, c1 = acc[mf][nf][1] * scale;
            float c2 = acc[mf][nf][2] * scale, c3 = acc[mf][nf][3] * scale;
            if (bias) {
                if (BIAS_ROW) {
                    float b0 = bias[rg], b8 = bias[rg + 8];
                    c0 += b0; c1 += b0; c2 += b8; c3 += b8;
                } else {
                    float b0 = bias[gn], b1 = bias[gn + 1];
                    c0 += b0; c1 += b1; c2 += b0; c3 += b1;
                }
            }
            if (RELU) {
                c0 = fmaxf(c0, 0.f); c1 = fmaxf(c1, 0.f);
                c2 = fmaxf(c2, 0.f); c3 = fmaxf(c3, 0.f);
            }
            const long long i0 = oC + (long long)rg * ldc + gn;
            const long long i8 = oC + (long long)(rg + 8) * ldc + gn;
            if (OUTM == 0) {
                *reinterpret_cast<float2*>(&Cf[i0]) = make_float2(c0, c1);
                *reinterpret_cast<float2*>(&Cf[i8]) = make_float2(c2, c3);
            } else if (OUTM == 1) {
                split2_store(c0, c1, &Chi[i0], &Clo[i0]);
                split2_store(c2, c3, &Chi[i8], &Clo[i8]);
            } else {
                float e0 = __expf(c0), e1 = __expf(c1);
                float e2 = __expf(c2), e3 = __expf(c3);
                *reinterpret_cast<float2*>(&Cf[i0]) = make_float2(e0, e1);
                *reinterpret_cast<float2*>(&Cf[i8]) = make_float2(e2, e3);
                p0 += e0 + e1; p8 += e2 + e3;
            }
        }
        if (OUTM == 2) {
            atomicAdd(&rs[lr], p0);
            atomicAdd(&rs[lr + 8], p8);
        }
    }
    if (OUTM == 2) {
        __syncthreads();
        if (tid < 128)
            atomicAdd(&rowsum[(long long)z * SS + row0 + tid], rs[tid]);
    }
}

/* ============ ctx kernel: normalize attn in place + ctx = P @ V ============
 * A = raw exp scores [SS, SS] fp32 (per b,h); per-row scale 1/rowsum; writes
 * normalized value back; splits to bf16 hi/lo smem; B = Vt hi/lo [DK, ROWS].
 * Output ctx hi/lo [B*S, D_MODEL] at column h*DK.  Tile 128 x 64 x 32.
 * Each of 2 n-warps covers 32 cols via NFP=2 fragment pairs.
 */
#define CTX_A   512               /* smem: inv[128] floats */
#define CTX_AH  (CTX_A)
#define CTX_AL  (CTX_AH + HMAT)
#define CTX_B   (CTX_AL + HMAT)
#define CTX_BH  (64*KSB)
#define CTX_BSTG (2*CTX_BH)
#define CTX_SMEM (CTX_B + 2*CTX_BSTG)

__global__ void __launch_bounds__(256, 2)
ctx_gemm(float* __restrict__ P, const float* __restrict__ rowsum,
         const bf16* __restrict__ Bhi, const bf16* __restrict__ Blo,
         bf16* __restrict__ Chi, bf16* __restrict__ Clo)
{
    extern __shared__ char smem[];
    const uint32_t sb = smem_u32(smem);
    const int tid = threadIdx.x, lane = tid & 31, wid = tid >> 5;
    const int z = blockIdx.y;                 /* b*NH + h */
    const int row0 = blockIdx.x * 128;

    P += (long long)z * SS * SS;
    const long long oB = (long long)(z & (N_HEADS - 1)) * DK * ROWS + (long long)(z / N_HEADS) * SS;
    Bhi += oB; Blo += oB;
    const long long oC = (long long)(z / N_HEADS) * SS * D_MODEL + (long long)(z & (N_HEADS - 1)) * DK;

    float* inv = reinterpret_cast<float*>(smem);
    if (tid < 128)
        inv[tid] = 1.f / rowsum[(long long)z * SS + row0 + tid];

    const int wm = wid & 3, wn = wid >> 2;
    const int m0 = wm * 32, n0 = wn * 32;
    const int r8 = lane & 7, sel = lane >> 3;
    const uint32_t aoff = (uint32_t)(m0 + (sel & 1) * 8 + r8) * KSB + (uint32_t)((sel >> 1) * 8) * 2u;
    const uint32_t boff = (uint32_t)(n0 + (sel >> 1) * 8 + r8) * KSB + (uint32_t)((sel & 1) * 8) * 2u;

    float acc[2][4][4];
#pragma unroll
    for (int i = 0; i < 2; i++)
#pragma unroll
        for (int j = 0; j < 4; j++)
#pragma unroll
            for (int q = 0; q < 4; q++) acc[i][j][q] = 0.f;

    auto issueB = [&](int it) {
        const int k0 = it * 32;
        const uint32_t s = sb + CTX_B + (uint32_t)(it & 1) * CTX_BSTG;
        int r = tid >> 2, c = tid & 3;        /* 64 rows x 4 f4cols */
        uint32_t d = s + (uint32_t)(r * KSB + c * 16);
        const long long go = (long long)r * ROWS + k0 + c * 8;
        CP16(d,          Bhi + go);
        CP16(d + CTX_BH, Blo + go);
        CPCOMMIT();
    };

    const int NCH = SS / 32;   /* 64 */
    float4 ar[4];
    auto loadA = [&](int it) {
        const int k0 = it * 32;
#pragma unroll
        for (int i = 0; i < 4; i++) {
            int e = tid + i * 256, r = e >> 3, c4 = e & 7;
            ar[i] = *reinterpret_cast<const float4*>(&P[(long long)(row0 + r) * SS + k0 + c4 * 4]);
        }
    };

    issueB(0);
    loadA(0);
    __syncthreads();   /* inv[] visible */

    for (int it = 0; it < NCH; ++it) {
        /* stage A: normalize, write back, split to hi/lo smem */
        const int k0 = it * 32;
#pragma unroll
        for (int i = 0; i < 4; i++) {
            int e = tid + i * 256, r = e >> 3, c4 = e & 7;
            float s = inv[r];
            float4 v = ar[i];
            v.x *= s; v.y *= s; v.z *= s; v.w *= s;
            *reinterpret_cast<float4*>(&P[(long long)(row0 + r) * SS + k0 + c4 * 4]) = v;
            uint2 hi, lo;
            split4r(v, hi, lo);
            uint32_t off = (uint32_t)(r * KSB + c4 * 8);
            *reinterpret_cast<uint2*>(smem + CTX_AH + off) = hi;
            *reinterpret_cast<uint2*>(smem + CTX_AL + off) = lo;
        }
        const bool more = (it + 1 < NCH);
        if (more) { issueB(it + 1); loadA(it + 1); CPWAIT(1); }
        else      { CPWAIT(0); }
        __syncthreads();

        const uint32_t bstg = sb + CTX_B + (uint32_t)(it & 1) * CTX_BSTG;
#pragma unroll
        for (int ks = 0; ks < 2; ++ks) {
            uint32_t ah[2][4], al[2][4];
#pragma unroll
            for (int mf = 0; mf < 2; ++mf) {
                uint32_t base = sb + CTX_AH + aoff + mf * (16 * KSB) + ks * 32;
                ldm4(ah[mf], base);
                ldm4(al[mf], base + HMAT);
            }
#pragma unroll
            for (int p = 0; p < 2; ++p) {
                uint32_t bb = bstg + boff + p * (16 * KSB) + ks * 32;
                uint32_t bh[4], bl[4];
                ldm4(bh, bb);
                ldm4(bl, bb + CTX_BH);
#pragma unroll
                for (int mf = 0; mf < 2; ++mf) {
                    mma_bf16(acc[mf][2 * p],     ah[mf], bh[0], bh[1]);
                    mma_bf16(acc[mf][2 * p + 1], ah[mf], bh[2], bh[3]);
                    mma_bf16(acc[mf][2 * p],     ah[mf], bl[0], bl[1]);
                    mma_bf16(acc[mf][2 * p + 1], ah[mf], bl[2], bl[3]);
                    mma_bf16(acc[mf][2 * p],     al[mf], bh[0], bh[1]);
                    mma_bf16(acc[mf][2 * p + 1], al[mf], bh[2], bh[3]);
                }
            }
        }
        __syncthreads();   /* A smem reused next iter */
    }

    /* epilogue -> ctx hi/lo */
    const int g2 = lane >> 2, l2 = lane & 3;
#pragma unroll
    for (int mf = 0; mf < 2; ++mf) {
        const int rg = row0 + m0 + mf * 16 + g2;
#pragma unroll
        for (int nf = 0; nf < 4; ++nf) {
            const int gcol = n0 + (nf >> 1) * 16 + (nf & 1) * 8 + l2 * 2;
            const long long i0 = oC + (long long)rg * D_MODEL + gcol;
            const long long i8 = oC + (long long)(rg + 8) * D_MODEL + gcol;
            split2_store(acc[mf][nf][0], acc[mf][nf][1], &Chi[i0], &Clo[i0]);
            split2_store(acc[mf][nf][2], acc[mf][nf][3], &Chi[i8], &Clo[i8]);
        }
    }
}

/* ---------- zero rowsum ---------- */
__global__ void zero_kernel(float* __restrict__ p, int n)
{
    int i = blockIdx.x * 256 + threadIdx.x;
    if (i < n) p[i] = 0.f;
}

/* ---------- fp32 -> bf16 hi/lo ---------- */
__global__ void split_kernel(const float* __restrict__ in, bf16* __restrict__ hi,
                             bf16* __restrict__ lo, int n4)
{
    int i = blockIdx.x * 256 + threadIdx.x;
    if (i >= n4) return;
    float4 v = reinterpret_cast<const float4*>(in)[i];
    uint2 h, l;
    split4r(v, h, l);
    reinterpret_cast<uint2*>(hi)[i] = h;
    reinterpret_cast<uint2*>(lo)[i] = l;
}

/* ---------- W[Kdim,Ndim] -> Wt hi/lo [Ndim,Kdim] ---------- */
__global__ void splitT_kernel(const float* __restrict__ W, bf16* __restrict__ thi,
                              bf16* __restrict__ tlo, int Kdim, int Ndim)
{
    __shared__ float t[32][33];
    const int n0 = blockIdx.x * 32, k0 = blockIdx.y * 32;
    const int tx = threadIdx.x, ty = threadIdx.y;
#pragma unroll
    for (int i = 0; i < 32; i += 8)
        t[ty + i][tx] = W[(long long)(k0 + ty + i) * Ndim + n0 + tx];
    __syncthreads();
#pragma unroll
    for (int i = 0; i < 32; i += 8) {
        float v = t[tx][ty + i];
        bf16 h = __float2bfloat16(v);
        bf16 l = __float2bfloat16(v - __bfloat162float(h));
        long long o = (long long)(n0 + ty + i) * Kdim + k0 + tx;
        thi[o] = h; tlo[o] = l;
    }
}

/* ------------- out = alpha*(v-mean)/(std+eps)+beta, v = x+y ------------- */
__global__ void add_ln_kernel(const float* __restrict__ x, const float* __restrict__ y,
                              const float* __restrict__ alpha, const float* __restrict__ beta,
                              float* __restrict__ out, bf16* __restrict__ ohi,
                              bf16* __restrict__ olo)
{
    __shared__ float v[D_MODEL];
    __shared__ float red[256];
    const int tid = threadIdx.x;
    const long long base = (long long)blockIdx.x * D_MODEL;

    float s = 0.f;
    for (int j = tid; j < D_MODEL; j += 256) {
        float t = x[base + j] + y[base + j];
        v[j] = t;
        s += t;
    }
    red[tid] = s; __syncthreads();
    for (int st = 128; st > 0; st >>= 1) {
        if (tid < st) red[tid] += red[tid + st];
        __syncthreads();
    }
    const float m = red[0] * (1.f / D_MODEL);
    __syncthreads();

    float c2 = 0.f;
    for (int j = tid; j < D_MODEL; j += 256) {
        float c = v[j] - m;
        c2 += c * c;
    }
    red[tid] = c2; __syncthreads();
    for (int st = 128; st > 0; st >>= 1) {
        if (tid < st) red[tid] += red[tid + st];
        __syncthreads();
    }
    const float stdv = sqrtf(red[0] / (float)(D_MODEL - 1));
    const float inv  = 1.f / (stdv + LN_EPS);
    for (int j = tid * 2; j < D_MODEL; j += 512) {
        float o0 = alpha[j] * (v[j] - m) * inv + beta[j];
        float o1 = alpha[j + 1] * (v[j + 1] - m) * inv + beta[j + 1];
        *reinterpret_cast<float2*>(&out[base + j]) = make_float2(o0, o1);
        if (ohi) split2_store(o0, o1, ohi + base + j, olo + base + j);
    }
}

/* ---------------- host dispatch ---------------- */
template<int BN_T, int OUTM, bool BIAS_ROW, bool RELU>
static void run_g(const bf16* Ahi, const bf16* Alo, const bf16* Bhi, const bf16* Blo,
                  const float* bias, float* Cf, bf16* Chi, bf16* Clo, float* rowsum,
                  int M, int N, int K, int lda, int ldb, int ldc,
                  int batch, int HB,
                  long long sA0, long long sA1, long long sB0, long long sB1,
                  long long sC0, long long sC1, float scale)
{
    cudaFuncSetAttribute((const void*)gemm_bf<BN_T, OUTM, BIAS_ROW, RELU>,
                         cudaFuncAttributeMaxDynamicSharedMemorySize, SMEM_TOTAL);
    dim3 grid(N / BN_T, M / 128, batch);
    gemm_bf<BN_T, OUTM, BIAS_ROW, RELU><<<grid, 256, SMEM_TOTAL>>>(
        Ahi, Alo, Bhi, Blo, bias, Cf, Chi, Clo, rowsum, K, lda, ldb, ldc,
        HB, sA0, sA1, sB0, sB1, sC0, sC1, scale);
}

#define GETSYM(var, sym) cudaGetSymbolAddress((void**)&var, sym)

extern "C" void kernel_launch(void* const* d_in, const int* in_sizes, int n_in,
                              void* d_out, int out_size)
{
    const float* x   = (const float*)d_in[0];
    const float* Wq  = (const float*)d_in[1];
    const float* bq  = (const float*)d_in[2];
    const float* Wk  = (const float*)d_in[3];
    const float* bk  = (const float*)d_in[4];
    const float* Wv  = (const float*)d_in[5];
    const float* bv  = (const float*)d_in[6];
    const float* Wo  = (const float*)d_in[7];
    const float* bo  = (const float*)d_in[8];
    const float* W1  = (const float*)d_in[9];
    const float* b1  = (const float*)d_in[10];
    const float* W2  = (const float*)d_in[11];
    const float* b2  = (const float*)d_in[12];
    const float* a1  = (const float*)d_in[13];
    const float* be1 = (const float*)d_in[14];
    const float* a2  = (const float*)d_in[15];
    const float* be2 = (const float*)d_in[16];

    float* out  = (float*)d_out;
    float* enc  = out;
    float* attn = out + (size_t)ROWS * D_MODEL;

    float *TMP, *AO, *F2, *RS;
    GETSYM(TMP, g_tmp); GETSYM(AO, g_ao); GETSYM(F2, g_f2); GETSYM(RS, g_rowsum);
    bf16 *xhi, *xlo, *wqhi, *wqlo, *wkhi, *wklo, *wvhi, *wvlo, *wohi, *wolo;
    bf16 *w1hi, *w1lo, *w2hi, *w2lo, *qhi, *qlo, *khi, *klo, *vthi, *vtlo;
    bf16 *chi, *clo, *aohi, *aolo, *f1hi, *f1lo;
    GETSYM(xhi, g_xhi);  GETSYM(xlo, g_xlo);
    GETSYM(wqhi, g_wqhi); GETSYM(wqlo, g_wqlo);
    GETSYM(wkhi, g_wkhi); GETSYM(wklo, g_wklo);
    GETSYM(wvhi, g_wvhi); GETSYM(wvlo, g_wvlo);
    GETSYM(wohi, g_wohi); GETSYM(wolo, g_wolo);
    GETSYM(w1hi, g_w1hi); GETSYM(w1lo, g_w1lo);
    GETSYM(w2hi, g_w2hi); GETSYM(w2lo, g_w2lo);
    GETSYM(qhi, g_qhi);   GETSYM(qlo, g_qlo);
    GETSYM(khi, g_khi);   GETSYM(klo, g_klo);
    GETSYM(vthi, g_vthi); GETSYM(vtlo, g_vtlo);
    GETSYM(chi, g_chi);   GETSYM(clo, g_clo);
    GETSYM(aohi, g_aohi); GETSYM(aolo, g_aolo);
    GETSYM(f1hi, g_f1hi); GETSYM(f1lo, g_f1lo);

    const long long sBD = (long long)SS * D_MODEL;
    const long long sSS = (long long)SS * SS;

    /* 0) conversions + rowsum zero */
    split_kernel<<<(ROWS * D_MODEL / 4 + 255) / 256, 256>>>(x, xhi, xlo, ROWS * D_MODEL / 4);
    dim3 tb(32, 8);
    splitT_kernel<<<dim3(D_MODEL / 32, D_MODEL / 32), tb>>>(Wq, wqhi, wqlo, D_MODEL, D_MODEL);
    splitT_kernel<<<dim3(D_MODEL / 32, D_MODEL / 32), tb>>>(Wk, wkhi, wklo, D_MODEL, D_MODEL);
    splitT_kernel<<<dim3(D_MODEL / 32, D_MODEL / 32), tb>>>(Wv, wvhi, wvlo, D_MODEL, D_MODEL);
    splitT_kernel<<<dim3(D_MODEL / 32, D_MODEL / 32), tb>>>(Wo, wohi, wolo, D_MODEL, D_MODEL);
    splitT_kernel<<<dim3(D_FF / 32, D_MODEL / 32),    tb>>>(W1, w1hi, w1lo, D_MODEL, D_FF);
    splitT_kernel<<<dim3(D_MODEL / 32, D_FF / 32),    tb>>>(W2, w2hi, w2lo, D_FF, D_MODEL);
    zero_kernel<<<(BB * N_HEADS * SS + 255) / 256, 256>>>(RS, BB * N_HEADS * SS);

    /* 1) Q, K, Vt projections */
    run_g<128, 1, false, false>(xhi, xlo, wqhi, wqlo, bq, nullptr, qhi, qlo, nullptr,
                                ROWS, D_MODEL, D_MODEL, D_MODEL, D_MODEL, D_MODEL,
                                1, 1, 0, 0, 0, 0, 0, 0, 1.f);
    run_g<128, 1, false, false>(xhi, xlo, wkhi, wklo, bk, nullptr, khi, klo, nullptr,
                                ROWS, D_MODEL, D_MODEL, D_MODEL, D_MODEL, D_MODEL,
                                1, 1, 0, 0, 0, 0, 0, 0, 1.f);
    run_g<128, 1, true, false>(wvhi, wvlo, xhi, xlo, bv, nullptr, vthi, vtlo, nullptr,
                               D_MODEL, ROWS, D_MODEL, D_MODEL, D_MODEL, ROWS,
                               1, 1, 0, 0, 0, 0, 0, 0, 1.f);

    /* 2) P~ = exp(QK^T/8) -> attn region + rowsums */
    run_g<128, 2, false, false>(qhi, qlo, khi, klo, nullptr, attn, nullptr, nullptr, RS,
                                SS, SS, DK, D_MODEL, D_MODEL, SS,
                                BB * N_HEADS, N_HEADS,
                                sBD, DK, sBD, DK,
                                (long long)N_HEADS * sSS, sSS, 0.125f);

    /* 3) ctx = P @ V fused with normalization + attn writeback */
    {
        cudaFuncSetAttribute((const void*)ctx_gemm,
                             cudaFuncAttributeMaxDynamicSharedMemorySize, CTX_SMEM);
        dim3 grid(SS / 128, BB * N_HEADS);
        ctx_gemm<<<grid, 256, CTX_SMEM>>>(attn, RS, vthi, vtlo, chi, clo);
    }

    /* 4) proj = ctx @ Wo + bo -> TMP */
    run_g<128, 0, false, false>(chi, clo, wohi, wolo, bo, TMP, nullptr, nullptr, nullptr,
                                ROWS, D_MODEL, D_MODEL, D_MODEL, D_MODEL, D_MODEL,
                                1, 1, 0, 0, 0, 0, 0, 0, 1.f);

    /* 5) attn_out = LN(x + proj) */
    add_ln_kernel<<<ROWS, 256>>>(x, TMP, a1, be1, AO, aohi, aolo);

    /* 6) ff1 = relu(AO @ W1 + b1) */
    run_g<128, 1, false, true>(aohi, aolo, w1hi, w1lo, b1, nullptr, f1hi, f1lo, nullptr,
                               ROWS, D_FF, D_MODEL, D_MODEL, D_MODEL, D_FF,
                               1, 1, 0, 0, 0, 0, 0, 0, 1.f);

    /* 7) ff2 = F1 @ W2 + b2 */
    run_g<128, 0, false, false>(f1hi, f1lo, w2hi, w2lo, b2, F2, nullptr, nullptr, nullptr,
                                ROWS, D_MODEL, D_FF, D_FF, D_FF, D_MODEL,
                                1, 1, 0, 0, 0, 0, 0, 0, 1.f);

    /* 8) enc_out = LN(AO + F2) */
    add_ln_kernel<<<ROWS, 256>>>(AO, F2, a2, be2, enc, nullptr, nullptr);

    (void)in_sizes; (void)n_in; (void)out_size;
}